// round 4
// baseline (speedup 1.0000x reference)
#include <cuda_runtime.h>
#include <cuda_bf16.h>
#include <cstdint>

// ---------------- problem constants ----------------
#define NFEAT  131072
#define DIM    128
#define KC     1024
#define TILE_M 128           // feature rows per CTA
#define CHN    128           // centers per B chunk
#define NCHUNK (KC / CHN)    // 8

// ---------------- smem layout (bytes, dynamic) ----------------
#define SA      0
#define SB0     32768
#define SB1     65536
#define S_BEST  98304                    // 2 * 128 float
#define S_IDX   (S_BEST + 1024)         // 2 * 128 int
#define S_RED   (S_IDX + 1024)          // 128 float
#define SM_TOTAL (S_RED + 512)

// ---------------- device scratch (allocation-free) ----------------
__device__ __nv_bfloat16 g_fbf[(size_t)NFEAT * DIM];   // normalized features, bf16
__device__ __nv_bfloat16 g_cbf[(size_t)KC * DIM];      // normalized centers, bf16
__device__ float g_cn[KC];                              // ||c||
__device__ float g_cn2[KC];                             // ||c||^2
__device__ float g_partial[NFEAT / TILE_M];             // per-CTA loss partials

// ---------------- ptx helpers (family-target-safe only) ----------------
__device__ __forceinline__ uint32_t smem_u32(const void* p) {
    uint32_t a;
    asm("{ .reg .u64 t; cvta.to.shared.u64 t, %1; cvt.u32.u64 %0, t; }" : "=r"(a) : "l"(p));
    return a;
}

#define CP_ASYNC16(dst, src) \
    asm volatile("cp.async.cg.shared.global [%0], [%1], 16;" :: "r"(dst), "l"(src) : "memory")
#define CP_COMMIT() asm volatile("cp.async.commit_group;" ::: "memory")
#define CP_WAIT(n)  asm volatile("cp.async.wait_group %0;" :: "n"(n) : "memory")

#define LDSM_X4(r0, r1, r2, r3, addr) \
    asm volatile("ldmatrix.sync.aligned.m8n8.x4.shared.b16 {%0,%1,%2,%3}, [%4];" \
                 : "=r"(r0), "=r"(r1), "=r"(r2), "=r"(r3) : "r"(addr))

#define MMA16816(d, a, b) \
    asm volatile("mma.sync.aligned.m16n8k16.row.col.f32.bf16.bf16.f32 " \
                 "{%0,%1,%2,%3}, {%4,%5,%6,%7}, {%8,%9}, {%0,%1,%2,%3};" \
                 : "+f"((d)[0]), "+f"((d)[1]), "+f"((d)[2]), "+f"((d)[3]) \
                 : "r"((a)[0]), "r"((a)[1]), "r"((a)[2]), "r"((a)[3]), \
                   "r"((b)[0]), "r"((b)[1]))

// ---------------- preprocessing: row L2-normalize -> bf16 ----------------
__global__ void __launch_bounds__(256) norm_feat_kernel(const float* __restrict__ f) {
    int row  = blockIdx.x * 8 + (threadIdx.x >> 5);
    int lane = threadIdx.x & 31;
    float4 v = reinterpret_cast<const float4*>(f)[(size_t)row * 32 + lane];
    float ss = fmaf(v.x, v.x, fmaf(v.y, v.y, fmaf(v.z, v.z, v.w * v.w)));
#pragma unroll
    for (int o = 16; o; o >>= 1) ss += __shfl_xor_sync(0xffffffffu, ss, o);
    float inv = 1.0f / fmaxf(sqrtf(ss), 1e-12f);
    __nv_bfloat162 h01 = __floats2bfloat162_rn(v.x * inv, v.y * inv);
    __nv_bfloat162 h23 = __floats2bfloat162_rn(v.z * inv, v.w * inv);
    uint2 u;
    u.x = *reinterpret_cast<uint32_t*>(&h01);
    u.y = *reinterpret_cast<uint32_t*>(&h23);
    reinterpret_cast<uint2*>(g_fbf)[(size_t)row * 32 + lane] = u;
}

__global__ void __launch_bounds__(256) norm_cent_kernel(const float* __restrict__ c) {
    int row  = blockIdx.x * 8 + (threadIdx.x >> 5);
    int lane = threadIdx.x & 31;
    float4 v = reinterpret_cast<const float4*>(c)[(size_t)row * 32 + lane];
    float ss = fmaf(v.x, v.x, fmaf(v.y, v.y, fmaf(v.z, v.z, v.w * v.w)));
#pragma unroll
    for (int o = 16; o; o >>= 1) ss += __shfl_xor_sync(0xffffffffu, ss, o);
    float n   = sqrtf(ss);
    float inv = 1.0f / fmaxf(n, 1e-12f);
    __nv_bfloat162 h01 = __floats2bfloat162_rn(v.x * inv, v.y * inv);
    __nv_bfloat162 h23 = __floats2bfloat162_rn(v.z * inv, v.w * inv);
    uint2 u;
    u.x = *reinterpret_cast<uint32_t*>(&h01);
    u.y = *reinterpret_cast<uint32_t*>(&h23);
    reinterpret_cast<uint2*>(g_cbf)[(size_t)row * 32 + lane] = u;
    if (lane == 0) { g_cn[row] = n; g_cn2[row] = ss; }
}

// ---------------- async swizzled tile load: [128 x 128] bf16, 256 B/row ----------------
// smem layout: row r at r*256; 16B chunk c stored at chunk (c ^ (r & 7))  -> conflict-free ldmatrix
__device__ __forceinline__ void load_tile_async(const __nv_bfloat16* __restrict__ src,
                                                uint32_t dst_base) {
#pragma unroll
    for (int it = 0; it < 8; it++) {
        int i = it * 256 + threadIdx.x;   // 2048 chunks of 16B
        int r = i >> 4;
        int c = i & 15;
        uint32_t dst = dst_base + r * 256 + ((c ^ (r & 7)) << 4);
        CP_ASYNC16(dst, reinterpret_cast<const char*>(src) + r * 256 + c * 16);
    }
}

// argmax update (strict > keeps lowest index within a thread's ascending column order)
__device__ __forceinline__ void amax_upd(float& b, int& bi, float v, int i) {
    if (v > b) { b = v; bi = i; }
}

// ---------------- main fused GEMM + argmax + loss kernel ----------------
__global__ void __launch_bounds__(256, 1) cluster_main_kernel() {
    extern __shared__ char smem[];
    uint32_t sbase = smem_u32(smem);
    int tid    = threadIdx.x;
    int wid    = tid >> 5;
    int lane   = tid & 31;
    int warp_m = wid & 3;        // 4 groups of 32 rows
    int warp_n = wid >> 2;       // 2 groups of 64 cols
    int lr     = lane & 7;
    int grp    = lane >> 3;

    // ---- prologue: A tile + first two B chunks in flight ----
    const __nv_bfloat16* fsrc = g_fbf + (size_t)blockIdx.x * TILE_M * DIM;
    load_tile_async(fsrc, sbase + SA);
    load_tile_async(g_cbf, sbase + SB0);
    CP_COMMIT();                                 // group 0: A + B0
    load_tile_async(g_cbf + CHN * DIM, sbase + SB1);
    CP_COMMIT();                                 // group 1: B1

    // ---- per-lane ldmatrix address prep ----
    // A frags (m16k16): mat0..3 = (m0-7,klo)(m8-15,klo)(m0-7,khi)(m8-15,khi)
    int rowA[2], r7a[2];
#pragma unroll
    for (int mi = 0; mi < 2; mi++) {
        rowA[mi] = warp_m * 32 + mi * 16 + lr + ((grp & 1) << 3);
        r7a[mi]  = rowA[mi] & 7;
    }
    int hiA = grp >> 1;
    // B frags (n16k16 pair): mat0..3 = (n0-7,klo)(n0-7,khi)(n8-15,klo)(n8-15,khi)
    uint32_t bRowOff[4];
    int r7b[4];
#pragma unroll
    for (int nt2 = 0; nt2 < 4; nt2++) {
        int row      = warp_n * 64 + nt2 * 16 + lr + ((grp >> 1) << 3);
        bRowOff[nt2] = row * 256;
        r7b[nt2]     = row & 7;
    }
    int hiB = grp & 1;

    uint32_t a_frag[2][8][4];     // A resident in registers across all chunks
    float    best[4] = {-3.4e38f, -3.4e38f, -3.4e38f, -3.4e38f};
    int      bidx[4] = {0, 0, 0, 0};

    for (int j = 0; j < NCHUNK; j++) {
        if (j < NCHUNK - 1) { CP_WAIT(1); } else { CP_WAIT(0); }
        __syncthreads();

        if (j == 0) {
            // preload A fragments once (A tile now resident in smem)
#pragma unroll
            for (int mi = 0; mi < 2; mi++)
#pragma unroll
                for (int ks = 0; ks < 8; ks++) {
                    uint32_t addr = sbase + SA + rowA[mi] * 256 +
                                    ((((ks << 1) + hiA) ^ r7a[mi]) << 4);
                    LDSM_X4(a_frag[mi][ks][0], a_frag[mi][ks][1],
                            a_frag[mi][ks][2], a_frag[mi][ks][3], addr);
                }
        }

        uint32_t bbuf = sbase + ((j & 1) ? SB1 : SB0);
        float acc[2][8][4];
#pragma unroll
        for (int mi = 0; mi < 2; mi++)
#pragma unroll
            for (int ni = 0; ni < 8; ni++)
#pragma unroll
                for (int q = 0; q < 4; q++) acc[mi][ni][q] = 0.f;

#pragma unroll
        for (int ks = 0; ks < 8; ks++) {
            uint32_t b[8][2];
#pragma unroll
            for (int nt2 = 0; nt2 < 4; nt2++) {
                uint32_t addr = bbuf + bRowOff[nt2] +
                                ((((ks << 1) + hiB) ^ r7b[nt2]) << 4);
                LDSM_X4(b[2 * nt2][0], b[2 * nt2][1],
                        b[2 * nt2 + 1][0], b[2 * nt2 + 1][1], addr);
            }
#pragma unroll
            for (int mi = 0; mi < 2; mi++)
#pragma unroll
                for (int ni = 0; ni < 8; ni++)
                    MMA16816(acc[mi][ni], a_frag[mi][ks], b[ni]);
        }

        // fold argmax of this 128-col chunk into running per-row (best, idx)
#pragma unroll
        for (int mi = 0; mi < 2; mi++)
#pragma unroll
            for (int ni = 0; ni < 8; ni++) {
                int cb = j * CHN + warp_n * 64 + ni * 8 + 2 * (lane & 3);
                amax_upd(best[2 * mi],     bidx[2 * mi],     acc[mi][ni][0], cb);
                amax_upd(best[2 * mi],     bidx[2 * mi],     acc[mi][ni][1], cb + 1);
                amax_upd(best[2 * mi + 1], bidx[2 * mi + 1], acc[mi][ni][2], cb);
                amax_upd(best[2 * mi + 1], bidx[2 * mi + 1], acc[mi][ni][3], cb + 1);
            }

        __syncthreads();   // everyone done reading buf (j&1) before it is refilled
        if (j < NCHUNK - 2) {
            load_tile_async(g_cbf + (size_t)(j + 2) * CHN * DIM,
                            sbase + (((j + 2) & 1) ? SB1 : SB0));
            CP_COMMIT();
        }
    }

    // ---- quad reduction: lanes 4r..4r+3 hold the same rows ----
#pragma unroll
    for (int off = 1; off <= 2; off <<= 1)
#pragma unroll
        for (int k = 0; k < 4; k++) {
            float ob = __shfl_xor_sync(0xffffffffu, best[k], off);
            int   oi = __shfl_xor_sync(0xffffffffu, bidx[k], off);
            if (ob > best[k] || (ob == best[k] && oi < bidx[k])) {
                best[k] = ob; bidx[k] = oi;
            }
        }

    float* smBest = reinterpret_cast<float*>(smem + S_BEST);
    int*   smIdx  = reinterpret_cast<int*>(smem + S_IDX);
    if ((lane & 3) == 0) {
        int rbase = warp_m * 32 + (lane >> 2);
#pragma unroll
        for (int k = 0; k < 4; k++) {
            int row = rbase + ((k & 1) << 3) + ((k >> 1) << 4);  // +0, +8, +16, +24
            smBest[warp_n * 128 + row] = best[k];
            smIdx [warp_n * 128 + row] = bidx[k];
        }
    }
    __syncthreads();

    // ---- combine the two warp_n halves, per-row loss, CTA reduce ----
    float* red = reinterpret_cast<float*>(smem + S_RED);
    if (tid < 128) {
        float b0 = smBest[tid];       int i0 = smIdx[tid];
        float b1 = smBest[128 + tid]; int i1 = smIdx[128 + tid];
        if (b1 > b0 || (b1 == b0 && i1 < i0)) { b0 = b1; i0 = i1; }
        // ||f_hat - c||^2 = 1 + ||c||^2 - 2 * s * ||c||   (f_hat is unit norm)
        red[tid] = 1.0f + g_cn2[i0] - 2.0f * b0 * g_cn[i0];
    }
    __syncthreads();
#pragma unroll
    for (int s = 64; s > 0; s >>= 1) {
        if (tid < s) red[tid] += red[tid + s];
        __syncthreads();
    }
    if (tid == 0) g_partial[blockIdx.x] = red[0];
}

// ---------------- deterministic final reduction ----------------
__global__ void __launch_bounds__(256) finalize_kernel(float* __restrict__ out) {
    __shared__ float sm[256];
    int t = threadIdx.x;
    float s = 0.f;
    for (int i = t; i < NFEAT / TILE_M; i += 256) s += g_partial[i];
    sm[t] = s;
    __syncthreads();
#pragma unroll
    for (int k = 128; k > 0; k >>= 1) {
        if (t < k) sm[t] += sm[t + k];
        __syncthreads();
    }
    if (t == 0) out[0] = sm[0] * (1.0f / (float)NFEAT);
}

// ---------------- launch ----------------
extern "C" void kernel_launch(void* const* d_in, const int* in_sizes, int n_in,
                              void* d_out, int out_size) {
    const float* feats = (const float*)d_in[0];  // [131072,128] fp32
    const float* cents = (const float*)d_in[1];  // [1024,128] fp32
    float* out = (float*)d_out;

    norm_feat_kernel<<<NFEAT / 8, 256>>>(feats);
    norm_cent_kernel<<<KC / 8, 256>>>(cents);

    cudaFuncSetAttribute(cluster_main_kernel,
                         cudaFuncAttributeMaxDynamicSharedMemorySize, SM_TOTAL);
    cluster_main_kernel<<<NFEAT / TILE_M, 256, SM_TOTAL>>>();

    finalize_kernel<<<1, 256>>>(out);
}